// round 3
// baseline (speedup 1.0000x reference)
#include <cuda_runtime.h>
#include <math.h>

#define BB 64
#define TT 256
#define FF 64
#define UU 512
#define G4U 2048
#define NROW (BB*TT)      // 16384
#define NCTA_REC 128

// ---------------- scratch (device globals: allocation-free rule) ----------------
__device__ float g_Xg[NROW * G4U];        // x@Wx+b per layer (134 MB, reused)
__device__ float g_H0[NROW * UU];         // h sequence, [b*T+t][U] layout
__device__ float g_H1[NROW * UU];
__device__ float g_Ht[TT * UU * BB];      // h sequence, step-major [t][u][b]
__device__ float g_zeros[BB * UU];        // never written -> zero-init
__device__ float g_cF[2 * BB * UU];
__device__ float g_hF[2 * BB * UU];
__device__ float g_cDump[BB * UU];
__device__ float g_hDump[BB * UU];
__device__ unsigned g_barCount = 0;
__device__ unsigned g_barGen = 0;

// ---------------- grid-wide barrier (all 128 CTAs co-resident, 1 CTA/SM) ----------------
__device__ __forceinline__ void grid_sync_all() {
    __syncthreads();
    if (threadIdx.x == 0) {
        __threadfence();
        unsigned gen = *(volatile unsigned*)&g_barGen;
        unsigned arr = atomicAdd(&g_barCount, 1u);
        if (arr == gridDim.x - 1) {
            g_barCount = 0;
            __threadfence();
            atomicAdd(&g_barGen, 1u);
        } else {
            while (*(volatile unsigned*)&g_barGen == gen) { }
        }
        __threadfence();
    }
    __syncthreads();
}

__device__ __forceinline__ float sigf(float x) { return 1.0f / (1.0f + expf(-x)); }

// ---------------- parallel GEMM: C[M,N] = A[M,K] @ W[K,N] + bias ----------------
__global__ __launch_bounds__(256) void xgemm_kernel(
    const float* __restrict__ A, const float* __restrict__ W,
    const float* __restrict__ bias, float* __restrict__ C,
    int M, int N, int K)
{
    __shared__ float As[16][68];   // As[k][m]
    __shared__ float Bs[16][68];   // Bs[k][n]
    const int tid = threadIdx.x;
    const int bm = blockIdx.y * 64;
    const int bn = blockIdx.x * 64;
    const int tx = tid & 15;
    const int ty = tid >> 4;
    const int lr  = tid >> 2;
    const int lkq = tid & 3;
    const int lk  = tid >> 4;
    const int lnq = tid & 15;

    float acc[4][4];
#pragma unroll
    for (int i = 0; i < 4; i++)
#pragma unroll
        for (int j = 0; j < 4; j++) acc[i][j] = 0.0f;

    for (int k0 = 0; k0 < K; k0 += 16) {
        float4 av = *(const float4*)(A + (size_t)(bm + lr) * K + k0 + lkq * 4);
        float4 wv = *(const float4*)(W + (size_t)(k0 + lk) * N + bn + lnq * 4);
        __syncthreads();
        As[lkq*4+0][lr] = av.x; As[lkq*4+1][lr] = av.y;
        As[lkq*4+2][lr] = av.z; As[lkq*4+3][lr] = av.w;
        *(float4*)&Bs[lk][lnq*4] = wv;
        __syncthreads();
#pragma unroll
        for (int kk = 0; kk < 16; ++kk) {
            float4 a = *(const float4*)&As[kk][ty*4];
            float4 b = *(const float4*)&Bs[kk][tx*4];
            acc[0][0] = fmaf(a.x, b.x, acc[0][0]); acc[0][1] = fmaf(a.x, b.y, acc[0][1]);
            acc[0][2] = fmaf(a.x, b.z, acc[0][2]); acc[0][3] = fmaf(a.x, b.w, acc[0][3]);
            acc[1][0] = fmaf(a.y, b.x, acc[1][0]); acc[1][1] = fmaf(a.y, b.y, acc[1][1]);
            acc[1][2] = fmaf(a.y, b.z, acc[1][2]); acc[1][3] = fmaf(a.y, b.w, acc[1][3]);
            acc[2][0] = fmaf(a.z, b.x, acc[2][0]); acc[2][1] = fmaf(a.z, b.y, acc[2][1]);
            acc[2][2] = fmaf(a.z, b.z, acc[2][2]); acc[2][3] = fmaf(a.z, b.w, acc[2][3]);
            acc[3][0] = fmaf(a.w, b.x, acc[3][0]); acc[3][1] = fmaf(a.w, b.y, acc[3][1]);
            acc[3][2] = fmaf(a.w, b.z, acc[3][2]); acc[3][3] = fmaf(a.w, b.w, acc[3][3]);
        }
    }
    float4 bv = *(const float4*)(bias + bn + tx * 4);
#pragma unroll
    for (int i = 0; i < 4; i++) {
        float4 o;
        o.x = acc[i][0] + bv.x; o.y = acc[i][1] + bv.y;
        o.z = acc[i][2] + bv.z; o.w = acc[i][3] + bv.w;
        *(float4*)(C + (size_t)(bm + ty*4 + i) * N + bn + tx * 4) = o;
    }
}

// ---------------- persistent LSTM recurrence ----------------
// gates(t) = Xg[b*T+t,:] + h(t-1) @ Wh, gate order (i,j,f,o) in 512-col blocks.
// CTA owns u-range [cta*4, cta*4+4) for ALL 4 gates & all 64 batch rows;
// c stays in registers for all T steps. Wh slice (512x16) cached in smem.
#define REC_SMEM ((512*68 + 16*65 + 512*16) * 4)   // 176,192 B

__global__ __launch_bounds__(256) void lstm_recur_kernel(
    const float* __restrict__ Xg, const float* __restrict__ Wh,
    const float* __restrict__ c_init, const float* __restrict__ h_init,
    float* __restrict__ Ht,                      // [t][u][b] step-major
    float* __restrict__ Hbt,                     // [b*T+t][U]
    float* __restrict__ c_fin, float* __restrict__ h_fin)
{
    extern __shared__ float sm[];
    float* hT = sm;                   // [512][68]  hT[u][b]
    float* gb = sm + 512 * 68;        // [16][65]   gate exchange
    float* ws = sm + 512 * 68 + 16 * 65;  // [512][16] Wh slice: ws[k][colIdx]

    const int tid = threadIdx.x;
    const int u0  = blockIdx.x * 4;
    // GEMM mapping: 16 cols (4 gates x 4 u) x 64 rows (4 per thread)
    const int colIdx = tid & 15;
    const int col = ((colIdx >> 2) << 9) + u0 + (colIdx & 3);  // gate*512 + u
    const int r0  = (tid >> 4) << 2;                            // batch row group
    // update mapping
    const int ub  = tid & 63;
    const int uuu = tid >> 6;
    const int myu = u0 + uuu;
    float creg = c_init[ub * UU + myu];

    // one-time: stage this CTA's Wh columns into smem
    for (int idx = tid; idx < 512 * 16; idx += 256) {
        int k = idx >> 4, ci = idx & 15;
        int wc = ((ci >> 2) << 9) + u0 + (ci & 3);
        ws[k * 16 + ci] = Wh[(size_t)k * G4U + wc];
    }

    for (int t = 0; t < TT; ++t) {
        // ---- stage h(t-1) into smem transposed hT[u][b] ----
        if (t == 0) {
            for (int idx = tid; idx < BB * UU; idx += 256) {
                int u = idx >> 6, b = idx & 63;
                hT[u * 68 + b] = h_init[b * UU + u];
            }
        } else {
            const float4* hp = (const float4*)(Ht + (size_t)(t - 1) * (UU * BB));
            for (int idx4 = tid; idx4 < (BB * UU) / 4; idx4 += 256) {
                int u = idx4 >> 4, b4 = idx4 & 15;
                *(float4*)(hT + u * 68 + b4 * 4) = hp[idx4];
            }
        }
        __syncthreads();

        // ---- gates = Xg + h @ Wh : 4 batch rows x 1 col per thread ----
        const float* xgp = Xg + (size_t)t * G4U + col;
        float a0 = xgp[(size_t)(r0 + 0) * TT * G4U];
        float a1 = xgp[(size_t)(r0 + 1) * TT * G4U];
        float a2 = xgp[(size_t)(r0 + 2) * TT * G4U];
        float a3 = xgp[(size_t)(r0 + 3) * TT * G4U];
#pragma unroll 8
        for (int k = 0; k < UU; ++k) {
            float w = ws[k * 16 + colIdx];
            float4 hv = *(const float4*)(hT + k * 68 + r0);
            a0 = fmaf(hv.x, w, a0);
            a1 = fmaf(hv.y, w, a1);
            a2 = fmaf(hv.z, w, a2);
            a3 = fmaf(hv.w, w, a3);
        }
        gb[colIdx * 65 + r0 + 0] = a0;
        gb[colIdx * 65 + r0 + 1] = a1;
        gb[colIdx * 65 + r0 + 2] = a2;
        gb[colIdx * 65 + r0 + 3] = a3;
        __syncthreads();

        // ---- cell update (CTA-local) ----
        float gi = gb[(0  + uuu) * 65 + ub];
        float gj = gb[(4  + uuu) * 65 + ub];
        float gf = gb[(8  + uuu) * 65 + ub];
        float go = gb[(12 + uuu) * 65 + ub];
        float cn = sigf(gf + 1.0f) * creg + sigf(gi) * tanhf(gj);
        float hn = sigf(go) * tanhf(cn);
        creg = cn;
        Ht[(size_t)t * (UU * BB) + myu * BB + ub] = hn;     // coalesced (hot path)
        Hbt[(size_t)(ub * TT + t) * UU + myu] = hn;         // cold path for next GEMM
        if (t == TT - 1) {
            c_fin[ub * UU + myu] = cn;
            h_fin[ub * UU + myu] = hn;
        }
        grid_sync_all();   // publish h(t)
    }
}

// ---------------- output projection + length mask ----------------
__global__ __launch_bounds__(256) void proj_kernel(
    const float* __restrict__ H, const float* __restrict__ Wo,
    const float* __restrict__ bo, const int* __restrict__ lens,
    float* __restrict__ out)
{
    __shared__ float hs[4][512];
    const int tid = threadIdx.x;
    const int row0 = blockIdx.x * 4;
    for (int idx = tid; idx < 4 * UU; idx += 256)
        hs[idx >> 9][idx & 511] = H[(size_t)row0 * UU + idx];
    __syncthreads();
    const int r = tid >> 6;
    const int c = tid & 63;
    float acc = bo[c];
#pragma unroll 8
    for (int k = 0; k < UU; ++k)
        acc = fmaf(hs[r][k], Wo[k * FF + c], acc);
    const int row = row0 + r;
    const int b = row >> 8;
    const int t = row & 255;
    out[(size_t)row * FF + c] = (t < lens[b]) ? acc : 0.0f;
}

// ---------------- launch ----------------
extern "C" void kernel_launch(void* const* d_in, const int* in_sizes, int n_in,
                              void* d_out, int out_size)
{
    const float* inputs  = (const float*)d_in[0];
    const float* targets = (const float*)d_in[1];
    const int*   tlen    = (const int*)d_in[2];
    const float* eW0 = (const float*)d_in[3];
    const float* eb0 = (const float*)d_in[4];
    const float* eW1 = (const float*)d_in[5];
    const float* eb1 = (const float*)d_in[6];
    const float* dW0 = (const float*)d_in[7];
    const float* db0 = (const float*)d_in[8];
    const float* dW1 = (const float*)d_in[9];
    const float* db1 = (const float*)d_in[10];
    const float* oW  = (const float*)d_in[11];
    const float* ob  = (const float*)d_in[12];
    float* out = (float*)d_out;

    float *Xg, *H0, *H1, *Ht, *zer, *cF, *hF, *cD, *hD;
    cudaGetSymbolAddress((void**)&Xg,  g_Xg);
    cudaGetSymbolAddress((void**)&H0,  g_H0);
    cudaGetSymbolAddress((void**)&H1,  g_H1);
    cudaGetSymbolAddress((void**)&Ht,  g_Ht);
    cudaGetSymbolAddress((void**)&zer, g_zeros);
    cudaGetSymbolAddress((void**)&cF,  g_cF);
    cudaGetSymbolAddress((void**)&hF,  g_hF);
    cudaGetSymbolAddress((void**)&cD,  g_cDump);
    cudaGetSymbolAddress((void**)&hD,  g_hDump);

    cudaFuncSetAttribute(lstm_recur_kernel,
                         cudaFuncAttributeMaxDynamicSharedMemorySize, REC_SMEM);

    dim3 gx(G4U / 64, NROW / 64);   // (32, 256)

    // encoder layer 0
    xgemm_kernel<<<gx, 256>>>(inputs, eW0, eb0, Xg, NROW, G4U, FF);
    lstm_recur_kernel<<<NCTA_REC, 256, REC_SMEM>>>(Xg, eW0 + (size_t)FF * G4U,
                                                   zer, zer, Ht, H0, cF, hF);
    // encoder layer 1
    xgemm_kernel<<<gx, 256>>>(H0, eW1, eb1, Xg, NROW, G4U, UU);
    lstm_recur_kernel<<<NCTA_REC, 256, REC_SMEM>>>(Xg, eW1 + (size_t)UU * G4U,
                                                   zer, zer, Ht, H1,
                                                   cF + BB * UU, hF + BB * UU);
    // decoder layer 0 (init = encoder layer-0 finals)
    xgemm_kernel<<<gx, 256>>>(targets, dW0, db0, Xg, NROW, G4U, FF);
    lstm_recur_kernel<<<NCTA_REC, 256, REC_SMEM>>>(Xg, dW0 + (size_t)FF * G4U,
                                                   cF, hF, Ht, H0, cD, hD);
    // decoder layer 1 (init = encoder layer-1 finals)
    xgemm_kernel<<<gx, 256>>>(H0, dW1, db1, Xg, NROW, G4U, UU);
    lstm_recur_kernel<<<NCTA_REC, 256, REC_SMEM>>>(Xg, dW1 + (size_t)UU * G4U,
                                                   cF + BB * UU, hF + BB * UU,
                                                   Ht, H1, cD, hD);
    // projection + mask
    proj_kernel<<<NROW / 4, 256>>>(H1, oW, ob, tlen, out);
}

// round 4
// speedup vs baseline: 1.2294x; 1.2294x over previous
#include <cuda_runtime.h>
#include <math.h>

#define BB 64
#define TT 256
#define FF 64
#define UU 512
#define G4U 2048
#define NROW (BB*TT)      // 16384
#define NCTA_REC 128

// ---------------- scratch (device globals: allocation-free rule) ----------------
__device__ float g_Xg[NROW * G4U];        // x@Wx+b per layer (134 MB, reused)
__device__ float g_H0[NROW * UU];         // h sequence, [b*T+t][U] layout
__device__ float g_H1[NROW * UU];
__device__ float g_Ht[TT * UU * BB];      // h sequence, step-major [t][u][b]
__device__ float g_zeros[BB * UU];        // never written -> zero-init
__device__ float g_cF[2 * BB * UU];
__device__ float g_hF[2 * BB * UU];
__device__ float g_cDump[BB * UU];
__device__ float g_hDump[BB * UU];
__device__ unsigned g_barCount = 0;
__device__ unsigned g_barGen = 0;

// ---------------- packed f32x2 helpers (Blackwell; ptxas never emits these) ----------------
typedef unsigned long long u64;

__device__ __forceinline__ u64 pack2(float lo, float hi) {
    u64 r; asm("mov.b64 %0, {%1, %2};" : "=l"(r) : "f"(lo), "f"(hi)); return r;
}
__device__ __forceinline__ u64 splat2(float v) {
    u64 r; asm("mov.b64 %0, {%1, %1};" : "=l"(r) : "f"(v)); return r;
}
__device__ __forceinline__ void unpack2(u64 p, float& lo, float& hi) {
    asm("mov.b64 {%0, %1}, %2;" : "=f"(lo), "=f"(hi) : "l"(p));
}
__device__ __forceinline__ u64 ffma2(u64 a, u64 b, u64 c) {
    u64 d; asm("fma.rn.f32x2 %0, %1, %2, %3;" : "=l"(d) : "l"(a), "l"(b), "l"(c)); return d;
}
__device__ __forceinline__ u64 fadd2(u64 a, u64 b) {
    u64 d; asm("add.rn.f32x2 %0, %1, %2;" : "=l"(d) : "l"(a), "l"(b)); return d;
}

// ---------------- grid-wide barrier (all 128 CTAs co-resident, 1 CTA/SM) ----------------
__device__ __forceinline__ void grid_sync_all() {
    __syncthreads();
    if (threadIdx.x == 0) {
        __threadfence();
        unsigned gen = *(volatile unsigned*)&g_barGen;
        unsigned arr = atomicAdd(&g_barCount, 1u);
        if (arr == gridDim.x - 1) {
            g_barCount = 0;
            __threadfence();
            atomicAdd(&g_barGen, 1u);
        } else {
            while (*(volatile unsigned*)&g_barGen == gen) { }
        }
        __threadfence();
    }
    __syncthreads();
}

__device__ __forceinline__ float sigf(float x) { return 1.0f / (1.0f + expf(-x)); }

// ---------------- parallel GEMM: C[M,N] = A[M,K] @ W[K,N] + bias (f32x2 core) ----------------
__global__ __launch_bounds__(256) void xgemm_kernel(
    const float* __restrict__ A, const float* __restrict__ W,
    const float* __restrict__ bias, float* __restrict__ C,
    int M, int N, int K)
{
    __shared__ float As[16][68];        // As[k][m]
    __shared__ float Bs2[16][136];      // splatted pairs: Bs2[k][2n..2n+1] = (b_n, b_n)
    const int tid = threadIdx.x;
    const int bm = blockIdx.y * 64;
    const int bn = blockIdx.x * 64;
    const int tx = tid & 15;       // n quad
    const int ty = tid >> 4;       // m quad
    const int lr  = tid >> 2;      // A load row
    const int lkq = tid & 3;       // A load k-quad
    const int lk  = tid >> 4;      // W load k
    const int lnq = tid & 15;      // W load n-quad

    u64 acc01[4], acc23[4];        // rows (m0,m1) and (m2,m3), 4 n each
#pragma unroll
    for (int j = 0; j < 4; j++) { acc01[j] = 0ull; acc23[j] = 0ull; }

    for (int k0 = 0; k0 < K; k0 += 16) {
        float4 av = *(const float4*)(A + (size_t)(bm + lr) * K + k0 + lkq * 4);
        float4 wv = *(const float4*)(W + (size_t)(k0 + lk) * N + bn + lnq * 4);
        __syncthreads();
        As[lkq*4+0][lr] = av.x; As[lkq*4+1][lr] = av.y;
        As[lkq*4+2][lr] = av.z; As[lkq*4+3][lr] = av.w;
        {
            ulonglong2 s01; s01.x = splat2(wv.x); s01.y = splat2(wv.y);
            ulonglong2 s23; s23.x = splat2(wv.z); s23.y = splat2(wv.w);
            *(ulonglong2*)&Bs2[lk][lnq*8]     = s01;
            *(ulonglong2*)&Bs2[lk][lnq*8 + 4] = s23;
        }
        __syncthreads();
#pragma unroll
        for (int kk = 0; kk < 16; ++kk) {
            ulonglong2 a  = *(const ulonglong2*)&As[kk][ty*4];     // (m0,m1),(m2,m3)
            ulonglong2 b0 = *(const ulonglong2*)&Bs2[kk][tx*8];    // (n0,n0),(n1,n1)
            ulonglong2 b1 = *(const ulonglong2*)&Bs2[kk][tx*8+4];  // (n2,n2),(n3,n3)
            acc01[0] = ffma2(a.x, b0.x, acc01[0]);
            acc01[1] = ffma2(a.x, b0.y, acc01[1]);
            acc01[2] = ffma2(a.x, b1.x, acc01[2]);
            acc01[3] = ffma2(a.x, b1.y, acc01[3]);
            acc23[0] = ffma2(a.y, b0.x, acc23[0]);
            acc23[1] = ffma2(a.y, b0.y, acc23[1]);
            acc23[2] = ffma2(a.y, b1.x, acc23[2]);
            acc23[3] = ffma2(a.y, b1.y, acc23[3]);
        }
    }
    float4 bv = *(const float4*)(bias + bn + tx * 4);
    float r0v[4], r1v[4], r2v[4], r3v[4];
#pragma unroll
    for (int j = 0; j < 4; j++) {
        unpack2(acc01[j], r0v[j], r1v[j]);
        unpack2(acc23[j], r2v[j], r3v[j]);
    }
    float4 o0 = make_float4(r0v[0]+bv.x, r0v[1]+bv.y, r0v[2]+bv.z, r0v[3]+bv.w);
    float4 o1 = make_float4(r1v[0]+bv.x, r1v[1]+bv.y, r1v[2]+bv.z, r1v[3]+bv.w);
    float4 o2 = make_float4(r2v[0]+bv.x, r2v[1]+bv.y, r2v[2]+bv.z, r2v[3]+bv.w);
    float4 o3 = make_float4(r3v[0]+bv.x, r3v[1]+bv.y, r3v[2]+bv.z, r3v[3]+bv.w);
    *(float4*)(C + (size_t)(bm + ty*4 + 0) * N + bn + tx * 4) = o0;
    *(float4*)(C + (size_t)(bm + ty*4 + 1) * N + bn + tx * 4) = o1;
    *(float4*)(C + (size_t)(bm + ty*4 + 2) * N + bn + tx * 4) = o2;
    *(float4*)(C + (size_t)(bm + ty*4 + 3) * N + bn + tx * 4) = o3;
}

// ---------------- persistent LSTM recurrence (512 thr, f32x2, 2-way k-split) ----------------
// gates(t) = Xg[b*T+t,:] + h(t-1) @ Wh, gate order (i,j,f,o) in 512-col blocks.
// CTA owns u-range [cta*4, cta*4+4) for all 4 gates & all 64 batch rows.
// smem: hT[512][68] + ws[512][16] + gb[16][72] + pb[256][4]
#define REC_SMEM ((512*68 + 512*16 + 16*72 + 256*4) * 4)   // 180,736 B

__global__ __launch_bounds__(512) void lstm_recur_kernel(
    const float* __restrict__ Xg, const float* __restrict__ Wh,
    const float* __restrict__ c_init, const float* __restrict__ h_init,
    float* __restrict__ Ht,                      // [t][u][b] step-major
    float* __restrict__ Hbt,                     // [b*T+t][U]
    float* __restrict__ c_fin, float* __restrict__ h_fin)
{
    extern __shared__ float sm[];
    float* hT = sm;                       // [512][68]
    float* ws = sm + 512*68;              // [512][16]
    float* gb = ws + 512*16;              // [16][72]
    float* pb = gb + 16*72;               // [256][4]

    const int tid = threadIdx.x;
    const int u0  = blockIdx.x * 4;
    const int colIdx = tid & 15;
    const int rowq = (tid >> 4) & 15;
    const int r0 = rowq * 4;
    const int ks = tid >> 8;                                   // k-split half
    const int col = ((colIdx >> 2) << 9) + u0 + (colIdx & 3);  // gate*512 + u
    // cell-update mapping (tid < 256 only)
    const int ub  = tid & 63;
    const int uuu = (tid >> 6) & 3;
    const int myu = u0 + uuu;
    float creg = (tid < 256) ? c_init[ub * UU + myu] : 0.0f;

    // stage Wh slice (512 x 16) into smem once
    for (int idx = tid; idx < 512 * 16; idx += 512) {
        int k = idx >> 4, ci = idx & 15;
        int wc = ((ci >> 2) << 9) + u0 + (ci & 3);
        ws[k * 16 + ci] = Wh[(size_t)k * G4U + wc];
    }

    const float* wp2 = ws + colIdx + (ks ? 256 * 16 : 0);
    const float* hp2base = (ks ? (const float*)0 : (const float*)0); // placeholder

    for (int t = 0; t < TT; ++t) {
        // ---- stage h(t-1) into smem transposed hT[u][b] ----
        if (t == 0) {
            for (int idx = tid; idx < BB * UU; idx += 512) {
                int u = idx >> 6, b = idx & 63;
                hT[u * 68 + b] = h_init[b * UU + u];
            }
        } else {
            const float4* hp = (const float4*)(Ht + (size_t)(t - 1) * (UU * BB));
            for (int idx4 = tid; idx4 < (BB * UU) / 4; idx4 += 512) {
                int u = idx4 >> 4, b4 = idx4 & 15;
                *(float4*)(hT + u * 68 + b4 * 4) = hp[idx4];
            }
        }
        __syncthreads();

        // Xg terms: issued now, consumed AFTER the k-loop (latency hidden under compute)
        float xa0 = 0.f, xa1 = 0.f, xa2 = 0.f, xa3 = 0.f;
        if (!ks) {
            const float* xgp = Xg + (size_t)t * G4U + col;
            xa0 = xgp[(size_t)(r0 + 0) * TT * G4U];
            xa1 = xgp[(size_t)(r0 + 1) * TT * G4U];
            xa2 = xgp[(size_t)(r0 + 2) * TT * G4U];
            xa3 = xgp[(size_t)(r0 + 3) * TT * G4U];
        }

        // ---- partial GEMM over this thread's 256 k's ----
        u64 p01 = 0ull, p23 = 0ull;
        const float* hp = hT + r0 + (ks ? 256 * 68 : 0);
#pragma unroll 8
        for (int kk = 0; kk < 256; ++kk) {
            u64 w2 = splat2(wp2[kk * 16]);
            ulonglong2 hv = *(const ulonglong2*)(hp + kk * 68);
            p01 = ffma2(hv.x, w2, p01);
            p23 = ffma2(hv.y, w2, p23);
        }

        if (ks) {
            ulonglong2 pv; pv.x = p01; pv.y = p23;
            *(ulonglong2*)(pb + (tid - 256) * 4) = pv;
        }
        __syncthreads();
        if (!ks) {
            ulonglong2 q = *(const ulonglong2*)(pb + tid * 4);
            p01 = fadd2(p01, q.x);
            p23 = fadd2(p23, q.y);
            p01 = fadd2(p01, pack2(xa0, xa1));
            p23 = fadd2(p23, pack2(xa2, xa3));
            float g0, g1, g2, g3;
            unpack2(p01, g0, g1);
            unpack2(p23, g2, g3);
            *(float4*)(gb + colIdx * 72 + r0) = make_float4(g0, g1, g2, g3);
        }
        __syncthreads();

        // ---- cell update (CTA-local) ----
        if (tid < 256) {
            float gi = gb[(0  + uuu) * 72 + ub];
            float gj = gb[(4  + uuu) * 72 + ub];
            float gf = gb[(8  + uuu) * 72 + ub];
            float go = gb[(12 + uuu) * 72 + ub];
            float cn = sigf(gf + 1.0f) * creg + sigf(gi) * tanhf(gj);
            float hn = sigf(go) * tanhf(cn);
            creg = cn;
            Ht[(size_t)t * (UU * BB) + myu * BB + ub] = hn;   // coalesced hot path
            Hbt[(size_t)(ub * TT + t) * UU + myu] = hn;       // cold path for next GEMM
            if (t == TT - 1) {
                c_fin[ub * UU + myu] = cn;
                h_fin[ub * UU + myu] = hn;
            }
        }
        grid_sync_all();   // publish h(t)
    }
}

// ---------------- output projection + length mask ----------------
__global__ __launch_bounds__(256) void proj_kernel(
    const float* __restrict__ H, const float* __restrict__ Wo,
    const float* __restrict__ bo, const int* __restrict__ lens,
    float* __restrict__ out)
{
    __shared__ float hs[4][512];
    const int tid = threadIdx.x;
    const int row0 = blockIdx.x * 4;
    for (int idx = tid; idx < 4 * UU; idx += 256)
        hs[idx >> 9][idx & 511] = H[(size_t)row0 * UU + idx];
    __syncthreads();
    const int r = tid >> 6;
    const int c = tid & 63;
    float acc = bo[c];
#pragma unroll 8
    for (int k = 0; k < UU; ++k)
        acc = fmaf(hs[r][k], Wo[k * FF + c], acc);
    const int row = row0 + r;
    const int b = row >> 8;
    const int t = row & 255;
    out[(size_t)row * FF + c] = (t < lens[b]) ? acc : 0.0f;
}

// ---------------- launch ----------------
extern "C" void kernel_launch(void* const* d_in, const int* in_sizes, int n_in,
                              void* d_out, int out_size)
{
    const float* inputs  = (const float*)d_in[0];
    const float* targets = (const float*)d_in[1];
    const int*   tlen    = (const int*)d_in[2];
    const float* eW0 = (const float*)d_in[3];
    const float* eb0 = (const float*)d_in[4];
    const float* eW1 = (const float*)d_in[5];
    const float* eb1 = (const float*)d_in[6];
    const float* dW0 = (const float*)d_in[7];
    const float* db0 = (const float*)d_in[8];
    const float* dW1 = (const float*)d_in[9];
    const float* db1 = (const float*)d_in[10];
    const float* oW  = (const float*)d_in[11];
    const float* ob  = (const float*)d_in[12];
    float* out = (float*)d_out;

    float *Xg, *H0, *H1, *Ht, *zer, *cF, *hF, *cD, *hD;
    cudaGetSymbolAddress((void**)&Xg,  g_Xg);
    cudaGetSymbolAddress((void**)&H0,  g_H0);
    cudaGetSymbolAddress((void**)&H1,  g_H1);
    cudaGetSymbolAddress((void**)&Ht,  g_Ht);
    cudaGetSymbolAddress((void**)&zer, g_zeros);
    cudaGetSymbolAddress((void**)&cF,  g_cF);
    cudaGetSymbolAddress((void**)&hF,  g_hF);
    cudaGetSymbolAddress((void**)&cD,  g_cDump);
    cudaGetSymbolAddress((void**)&hD,  g_hDump);

    cudaFuncSetAttribute(lstm_recur_kernel,
                         cudaFuncAttributeMaxDynamicSharedMemorySize, REC_SMEM);

    dim3 gx(G4U / 64, NROW / 64);   // (32, 256)

    // encoder layer 0
    xgemm_kernel<<<gx, 256>>>(inputs, eW0, eb0, Xg, NROW, G4U, FF);
    lstm_recur_kernel<<<NCTA_REC, 512, REC_SMEM>>>(Xg, eW0 + (size_t)FF * G4U,
                                                   zer, zer, Ht, H0, cF, hF);
    // encoder layer 1
    xgemm_kernel<<<gx, 256>>>(H0, eW1, eb1, Xg, NROW, G4U, UU);
    lstm_recur_kernel<<<NCTA_REC, 512, REC_SMEM>>>(Xg, eW1 + (size_t)UU * G4U,
                                                   zer, zer, Ht, H1,
                                                   cF + BB * UU, hF + BB * UU);
    // decoder layer 0 (init = encoder layer-0 finals)
    xgemm_kernel<<<gx, 256>>>(targets, dW0, db0, Xg, NROW, G4U, FF);
    lstm_recur_kernel<<<NCTA_REC, 512, REC_SMEM>>>(Xg, dW0 + (size_t)FF * G4U,
                                                   cF, hF, Ht, H0, cD, hD);
    // decoder layer 1 (init = encoder layer-1 finals)
    xgemm_kernel<<<gx, 256>>>(H0, dW1, db1, Xg, NROW, G4U, UU);
    lstm_recur_kernel<<<NCTA_REC, 512, REC_SMEM>>>(Xg, dW1 + (size_t)UU * G4U,
                                                   cF + BB * UU, hF + BB * UU,
                                                   Ht, H1, cD, hD);
    // projection + mask
    proj_kernel<<<NROW / 4, 256>>>(H1, oW, ob, tlen, out);
}